// round 11
// baseline (speedup 1.0000x reference)
#include <cuda_runtime.h>
#include <cuda_fp16.h>
#include <mma.h>
#include <cstdint>

using namespace nvcuda;

#define MAXN 100000
#define C 64
#define BUCKET_CAP 64

// Scratch (allocation-free rule: __device__ globals)
__device__ float g_dis[MAXN];
__device__ int   g_cursor[MAXN];
__device__ __align__(16) float2  g_bucket[(size_t)MAXN * BUCKET_CAP]; // {row_bits, ew}
__device__ __align__(16) __half2 g_xwh[(size_t)MAXN * (C / 2)];       // fp16 dis[r]*xw[r]
__device__ __align__(16) __half2 g_hh[(size_t)MAXN * (C / 2)];        // fp16 relu(h)

// ---------------------------------------------------------------------------
__global__ void init_kernel(int n) {
    int i = blockIdx.x * blockDim.x + threadIdx.x;
    if (i < n) g_cursor[i] = 0;
}

// Bucket edges by destination node: bucket[c][pos] = {row, ew}
__global__ void place_kernel(const int* __restrict__ ei,
                             const float* __restrict__ ew, int E) {
    int e = blockIdx.x * blockDim.x + threadIdx.x;
    if (e >= E) return;
    int r = ei[e];
    int c = ei[E + e];
    int pos = atomicAdd(&g_cursor[c], 1);
    if (pos < BUCKET_CAP)
        g_bucket[(size_t)c * BUCKET_CAP + pos] =
            make_float2(__int_as_float(r), ew[e]);
}

// dis[v] = rsqrt(1 + sum of bucket ew)  — warp per node, no second edge pass
__global__ void __launch_bounds__(256)
dis_from_bucket_kernel(int n) {
    int v = blockIdx.x * 8 + (threadIdx.x >> 5);
    if (v >= n) return;
    int lane = threadIdx.x & 31;
    int d = g_cursor[v];
    if (d > BUCKET_CAP) d = BUCKET_CAP;
    const float2* bk = &g_bucket[(size_t)v * BUCKET_CAP];
    float s = 0.f;
    if (lane < d)      s  = bk[lane].y;
    if (lane + 32 < d) s += bk[lane + 32].y;
    #pragma unroll
    for (int o = 16; o; o >>= 1) s += __shfl_xor_sync(0xFFFFFFFFu, s, o);
    if (lane == 0) g_dis[v] = rsqrtf(1.0f + s);
}

// ---------------------------------------------------------------------------
// Tensor-core GEMM producing ONLY the fp16 message: m = fp16(dis[r] * (in@W)).
#define XH_LD 72
#define OS_LD 68
#define SMEM_BYTES 34816

__global__ void __launch_bounds__(256)
gemm_msg_kernel(const void* __restrict__ in, int in_half,
                const float* __restrict__ W,
                __half2* __restrict__ xwh,
                int n) {
    __shared__ __align__(16) char smem_raw[SMEM_BYTES];
    __half (*xh)[XH_LD] = reinterpret_cast<__half(*)[XH_LD]>(smem_raw);
    __half (*wh)[XH_LD] = reinterpret_cast<__half(*)[XH_LD]>(smem_raw + 18432);
    float  (*osm)[OS_LD] = reinterpret_cast<float(*)[OS_LD]>(smem_raw);

    int t = threadIdx.x;
    int rowBase = blockIdx.x * 128;

    for (int i = t; i < C * C; i += 256)
        wh[i >> 6][i & 63] = __float2half(W[i]);

    if (!in_half) {
        const float* inf = (const float*)in;
        #pragma unroll
        for (int i = 0; i < 8; ++i) {
            int idx = t + i * 256;
            int row = idx >> 4;
            int c4  = idx & 15;
            float4 v = make_float4(0.f, 0.f, 0.f, 0.f);
            int gr = rowBase + row;
            if (gr < n) v = ((const float4*)(inf + (size_t)gr * C))[c4];
            __half2* d = reinterpret_cast<__half2*>(&xh[row][c4 * 4]);
            d[0] = __floats2half2_rn(v.x, v.y);
            d[1] = __floats2half2_rn(v.z, v.w);
        }
    } else {
        const int4* inh = (const int4*)in;
        #pragma unroll
        for (int i = 0; i < 4; ++i) {
            int idx = t + i * 256;
            int row = idx >> 3;
            int c8  = idx & 7;
            int4 v = make_int4(0, 0, 0, 0);
            int gr = rowBase + row;
            if (gr < n) v = inh[(size_t)gr * 8 + c8];
            *reinterpret_cast<int4*>(&xh[row][c8 * 8]) = v;
        }
    }
    __syncthreads();

    int warp = t >> 5;
    wmma::fragment<wmma::accumulator, 16, 16, 16, float> cf[4];
    #pragma unroll
    for (int j = 0; j < 4; ++j) wmma::fill_fragment(cf[j], 0.0f);

    #pragma unroll
    for (int k = 0; k < 4; ++k) {
        wmma::fragment<wmma::matrix_a, 16, 16, 16, __half, wmma::row_major> af;
        wmma::load_matrix_sync(af, &xh[warp * 16][k * 16], XH_LD);
        #pragma unroll
        for (int j = 0; j < 4; ++j) {
            wmma::fragment<wmma::matrix_b, 16, 16, 16, __half, wmma::row_major> bf;
            wmma::load_matrix_sync(bf, &wh[k * 16][j * 16], XH_LD);
            wmma::mma_sync(cf[j], af, bf, cf[j]);
        }
    }
    __syncthreads();

    #pragma unroll
    for (int j = 0; j < 4; ++j)
        wmma::store_matrix_sync(&osm[warp * 16][j * 16], cf[j], OS_LD,
                                wmma::mem_row_major);
    __syncthreads();

    int tx2 = t & 15;
    int ry  = (t >> 4) * 8;
    #pragma unroll
    for (int i = 0; i < 8; ++i) {
        int row = ry + i;
        int r = rowBase + row;
        if (r < n) {
            float4 s = *(const float4*)&osm[row][tx2 * 4];
            float d = g_dis[r];
            __half2* hp = &xwh[(size_t)r * (C / 2) + tx2 * 2];
            hp[0] = __floats2half2_rn(d * s.x, d * s.y);
            hp[1] = __floats2half2_rn(d * s.z, d * s.w);
        }
    }
}

// ---------------------------------------------------------------------------
// Gather + epilogue, 4-way MLP: s = b[c] + dis[v]*m[v] + messages.
__global__ void __launch_bounds__(256)
gather_sum_kernel(const __half2* __restrict__ xwh,
                  const float* __restrict__ bias,
                  __half2* __restrict__ dsth,
                  float* __restrict__ dstf,
                  int store_half, int n) {
    int v = blockIdx.x * 8 + (threadIdx.x >> 5);
    if (v >= n) return;
    int lane = threadIdx.x & 31;

    int d = g_cursor[v];
    if (d > BUCKET_CAP) d = BUCKET_CAP;
    float dv = g_dis[v];

    float2 bvv = *(const float2*)&bias[lane * 2];
    float2 mv  = __half22float2(xwh[(size_t)v * (C / 2) + lane]);
    float2 s   = make_float2(fmaf(dv, mv.x, bvv.x), fmaf(dv, mv.y, bvv.y));

    const float2* bk = &g_bucket[(size_t)v * BUCKET_CAP];

    int j = 0;
    for (; j + 4 <= d; j += 4) {
        // 4 records as two lane-uniform float4 loads (one 32B segment)
        float4 q01 = *(const float4*)&bk[j];
        float4 q23 = *(const float4*)&bk[j + 2];
        int r0 = __float_as_int(q01.x), r1 = __float_as_int(q01.z);
        int r2 = __float_as_int(q23.x), r3 = __float_as_int(q23.z);
        // 4 independent row loads issued before any use (MLP=4)
        float2 v0 = __half22float2(xwh[(size_t)r0 * (C / 2) + lane]);
        float2 v1 = __half22float2(xwh[(size_t)r1 * (C / 2) + lane]);
        float2 v2 = __half22float2(xwh[(size_t)r2 * (C / 2) + lane]);
        float2 v3 = __half22float2(xwh[(size_t)r3 * (C / 2) + lane]);
        float n0 = q01.y * dv, n1 = q01.w * dv;
        float n2 = q23.y * dv, n3 = q23.w * dv;
        s.x = fmaf(n0, v0.x, s.x); s.y = fmaf(n0, v0.y, s.y);
        s.x = fmaf(n1, v1.x, s.x); s.y = fmaf(n1, v1.y, s.y);
        s.x = fmaf(n2, v2.x, s.x); s.y = fmaf(n2, v2.y, s.y);
        s.x = fmaf(n3, v3.x, s.x); s.y = fmaf(n3, v3.y, s.y);
    }
    for (; j < d; ++j) {
        float2 rn = bk[j];
        int r = __float_as_int(rn.x);
        float nn = rn.y * dv;
        float2 vv = __half22float2(xwh[(size_t)r * (C / 2) + lane]);
        s.x = fmaf(nn, vv.x, s.x); s.y = fmaf(nn, vv.y, s.y);
    }

    if (store_half) {
        dsth[(size_t)v * (C / 2) + lane] =
            __floats2half2_rn(fmaxf(s.x, 0.f), fmaxf(s.y, 0.f));
    } else {
        *(float2*)&dstf[(size_t)v * C + lane * 2] = s;
    }
}

// ---------------------------------------------------------------------------
extern "C" void kernel_launch(void* const* d_in, const int* in_sizes, int n_in,
                              void* d_out, int out_size) {
    const float* x  = (const float*)d_in[0];
    const int*   ei = (const int*)d_in[1];     // int32 (JAX x64 disabled)
    const float* ew = (const float*)d_in[2];
    const float* W1 = (const float*)d_in[3];
    const float* b1 = (const float*)d_in[4];
    const float* W2 = (const float*)d_in[5];
    const float* b2 = (const float*)d_in[6];
    float*       out = (float*)d_out;

    int N = in_sizes[0] / C;
    int E = in_sizes[2];

    __half2 *p_xwh, *p_hh;
    cudaGetSymbolAddress((void**)&p_xwh, g_xwh);
    cudaGetSymbolAddress((void**)&p_hh,  g_hh);

    const int TB = 256;
    int edge_grid = (E + TB - 1) / TB;
    int node_grid = (N + TB - 1) / TB;
    int warp8_grid = (N + 7) / 8;
    int gemm_grid = (N + 127) / 128;

    // Prologue: cursor reset -> buckets -> dis from buckets (no deg pass)
    init_kernel<<<node_grid, TB>>>(N);
    place_kernel<<<edge_grid, TB>>>(ei, ew, E);
    dis_from_bucket_kernel<<<warp8_grid, TB>>>(N);

    // Layer 1: m = fp16(dis*(x@W1)); h = fp16(relu(b1 + selfloop + messages))
    gemm_msg_kernel<<<gemm_grid, TB>>>(x, 0, W1, p_xwh, N);
    gather_sum_kernel<<<warp8_grid, TB>>>(p_xwh, b1, p_hh, nullptr, 1, N);

    // Layer 2: m = fp16(dis*(h@W2)); out = b2 + selfloop + messages (fp32)
    gemm_msg_kernel<<<gemm_grid, TB>>>(p_hh, 1, W2, p_xwh, N);
    gather_sum_kernel<<<warp8_grid, TB>>>(p_xwh, b2, nullptr, out, 0, N);
}

// round 12
// speedup vs baseline: 1.0497x; 1.0497x over previous
#include <cuda_runtime.h>
#include <cuda_fp16.h>
#include <mma.h>
#include <cstdint>

using namespace nvcuda;

#define MAXN 100000
#define C 64
#define BUCKET_CAP 64

// Scratch (allocation-free rule: __device__ globals)
__device__ float g_deg[MAXN];
__device__ float g_dis[MAXN];
__device__ int   g_cursor[MAXN];
__device__ __align__(16) float2  g_bucket[(size_t)MAXN * BUCKET_CAP]; // {row_bits, ew}
__device__ __align__(16) __half2 g_xwh[(size_t)MAXN * (C / 2)];       // fp16 dis[r]*xw[r]
__device__ __align__(16) __half2 g_hh[(size_t)MAXN * (C / 2)];        // fp16 relu(h)

// ---------------------------------------------------------------------------
__global__ void init_kernel(int n) {
    int i = blockIdx.x * blockDim.x + threadIdx.x;
    if (i < n) { g_deg[i] = 1.0f; g_cursor[i] = 0; }   // self-loop weight
}

__global__ void deg_accum_kernel(const int* __restrict__ ei,
                                 const float* __restrict__ ew, int E) {
    int e = blockIdx.x * blockDim.x + threadIdx.x;
    if (e < E) atomicAdd(&g_deg[ei[E + e]], ew[e]);
}

__global__ void dis_kernel(int n) {
    int i = blockIdx.x * blockDim.x + threadIdx.x;
    if (i < n) g_dis[i] = rsqrtf(g_deg[i]);
}

// Bucket edges by destination: 4 edges per thread, block-tiled for coalescing.
// 4 independent atomic->store chains in flight per thread (MLP=4).
__global__ void __launch_bounds__(256)
place_kernel(const int* __restrict__ ei, const float* __restrict__ ew, int E) {
    int base = blockIdx.x * 1024 + threadIdx.x;

    int   r[4], c[4];
    float w[4];
    int   pos[4];
    #pragma unroll
    for (int k = 0; k < 4; ++k) {
        int e = base + k * 256;
        if (e < E) {
            r[k] = ei[e];
            c[k] = ei[E + e];
            w[k] = ew[e];
        } else c[k] = -1;
    }
    #pragma unroll
    for (int k = 0; k < 4; ++k)
        if (c[k] >= 0) pos[k] = atomicAdd(&g_cursor[c[k]], 1);
    #pragma unroll
    for (int k = 0; k < 4; ++k)
        if (c[k] >= 0 && pos[k] < BUCKET_CAP)
            g_bucket[(size_t)c[k] * BUCKET_CAP + pos[k]] =
                make_float2(__int_as_float(r[k]), w[k]);
}

// ---------------------------------------------------------------------------
// Tensor-core GEMM producing ONLY the fp16 message: m = fp16(dis[r] * (in@W)).
#define XH_LD 72
#define OS_LD 68
#define SMEM_BYTES 34816

__global__ void __launch_bounds__(256)
gemm_msg_kernel(const void* __restrict__ in, int in_half,
                const float* __restrict__ W,
                __half2* __restrict__ xwh,
                int n) {
    __shared__ __align__(16) char smem_raw[SMEM_BYTES];
    __half (*xh)[XH_LD] = reinterpret_cast<__half(*)[XH_LD]>(smem_raw);
    __half (*wh)[XH_LD] = reinterpret_cast<__half(*)[XH_LD]>(smem_raw + 18432);
    float  (*osm)[OS_LD] = reinterpret_cast<float(*)[OS_LD]>(smem_raw);

    int t = threadIdx.x;
    int rowBase = blockIdx.x * 128;

    for (int i = t; i < C * C; i += 256)
        wh[i >> 6][i & 63] = __float2half(W[i]);

    if (!in_half) {
        const float* inf = (const float*)in;
        #pragma unroll
        for (int i = 0; i < 8; ++i) {
            int idx = t + i * 256;
            int row = idx >> 4;
            int c4  = idx & 15;
            float4 v = make_float4(0.f, 0.f, 0.f, 0.f);
            int gr = rowBase + row;
            if (gr < n) v = ((const float4*)(inf + (size_t)gr * C))[c4];
            __half2* d = reinterpret_cast<__half2*>(&xh[row][c4 * 4]);
            d[0] = __floats2half2_rn(v.x, v.y);
            d[1] = __floats2half2_rn(v.z, v.w);
        }
    } else {
        const int4* inh = (const int4*)in;
        #pragma unroll
        for (int i = 0; i < 4; ++i) {
            int idx = t + i * 256;
            int row = idx >> 3;
            int c8  = idx & 7;
            int4 v = make_int4(0, 0, 0, 0);
            int gr = rowBase + row;
            if (gr < n) v = inh[(size_t)gr * 8 + c8];
            *reinterpret_cast<int4*>(&xh[row][c8 * 8]) = v;
        }
    }
    __syncthreads();

    int warp = t >> 5;
    wmma::fragment<wmma::accumulator, 16, 16, 16, float> cf[4];
    #pragma unroll
    for (int j = 0; j < 4; ++j) wmma::fill_fragment(cf[j], 0.0f);

    #pragma unroll
    for (int k = 0; k < 4; ++k) {
        wmma::fragment<wmma::matrix_a, 16, 16, 16, __half, wmma::row_major> af;
        wmma::load_matrix_sync(af, &xh[warp * 16][k * 16], XH_LD);
        #pragma unroll
        for (int j = 0; j < 4; ++j) {
            wmma::fragment<wmma::matrix_b, 16, 16, 16, __half, wmma::row_major> bf;
            wmma::load_matrix_sync(bf, &wh[k * 16][j * 16], XH_LD);
            wmma::mma_sync(cf[j], af, bf, cf[j]);
        }
    }
    __syncthreads();

    #pragma unroll
    for (int j = 0; j < 4; ++j)
        wmma::store_matrix_sync(&osm[warp * 16][j * 16], cf[j], OS_LD,
                                wmma::mem_row_major);
    __syncthreads();

    int tx2 = t & 15;
    int ry  = (t >> 4) * 8;
    #pragma unroll
    for (int i = 0; i < 8; ++i) {
        int row = ry + i;
        int r = rowBase + row;
        if (r < n) {
            float4 s = *(const float4*)&osm[row][tx2 * 4];
            float d = g_dis[r];
            __half2* hp = &xwh[(size_t)r * (C / 2) + tx2 * 2];
            hp[0] = __floats2half2_rn(d * s.x, d * s.y);
            hp[1] = __floats2half2_rn(d * s.z, d * s.w);
        }
    }
}

// ---------------------------------------------------------------------------
// Gather + epilogue (R10-proven 2-unroll): s = b[c] + dis[v]*m[v] + messages.
__global__ void __launch_bounds__(256)
gather_sum_kernel(const __half2* __restrict__ xwh,
                  const float* __restrict__ bias,
                  __half2* __restrict__ dsth,
                  float* __restrict__ dstf,
                  int store_half, int n) {
    int v = blockIdx.x * 8 + (threadIdx.x >> 5);
    if (v >= n) return;
    int lane = threadIdx.x & 31;

    int d = g_cursor[v];
    if (d > BUCKET_CAP) d = BUCKET_CAP;
    float dv = g_dis[v];

    float2 bvv = *(const float2*)&bias[lane * 2];
    float2 mv  = __half22float2(xwh[(size_t)v * (C / 2) + lane]);
    float2 s   = make_float2(fmaf(dv, mv.x, bvv.x), fmaf(dv, mv.y, bvv.y));

    const float2* bk = &g_bucket[(size_t)v * BUCKET_CAP];

    int j = 0;
    for (; j + 2 <= d; j += 2) {
        float2 rn0 = bk[j];
        float2 rn1 = bk[j + 1];
        int r0 = __float_as_int(rn0.x);
        int r1 = __float_as_int(rn1.x);
        float n0 = rn0.y * dv;
        float n1 = rn1.y * dv;
        float2 v0 = __half22float2(xwh[(size_t)r0 * (C / 2) + lane]);
        float2 v1 = __half22float2(xwh[(size_t)r1 * (C / 2) + lane]);
        s.x = fmaf(n0, v0.x, s.x); s.y = fmaf(n0, v0.y, s.y);
        s.x = fmaf(n1, v1.x, s.x); s.y = fmaf(n1, v1.y, s.y);
    }
    if (j < d) {
        float2 rn = bk[j];
        int r = __float_as_int(rn.x);
        float nn = rn.y * dv;
        float2 vv = __half22float2(xwh[(size_t)r * (C / 2) + lane]);
        s.x = fmaf(nn, vv.x, s.x); s.y = fmaf(nn, vv.y, s.y);
    }

    if (store_half) {
        dsth[(size_t)v * (C / 2) + lane] =
            __floats2half2_rn(fmaxf(s.x, 0.f), fmaxf(s.y, 0.f));
    } else {
        *(float2*)&dstf[(size_t)v * C + lane * 2] = s;
    }
}

// ---------------------------------------------------------------------------
extern "C" void kernel_launch(void* const* d_in, const int* in_sizes, int n_in,
                              void* d_out, int out_size) {
    const float* x  = (const float*)d_in[0];
    const int*   ei = (const int*)d_in[1];     // int32 (JAX x64 disabled)
    const float* ew = (const float*)d_in[2];
    const float* W1 = (const float*)d_in[3];
    const float* b1 = (const float*)d_in[4];
    const float* W2 = (const float*)d_in[5];
    const float* b2 = (const float*)d_in[6];
    float*       out = (float*)d_out;

    int N = in_sizes[0] / C;
    int E = in_sizes[2];

    __half2 *p_xwh, *p_hh;
    cudaGetSymbolAddress((void**)&p_xwh, g_xwh);
    cudaGetSymbolAddress((void**)&p_hh,  g_hh);

    const int TB = 256;
    int edge_grid  = (E + TB - 1) / TB;
    int place_grid = (E + 1023) / 1024;     // 4 edges per thread
    int node_grid  = (N + TB - 1) / TB;
    int warp8_grid = (N + 7) / 8;
    int gemm_grid  = (N + 127) / 128;

    // Prologue (R10 order)
    init_kernel<<<node_grid, TB>>>(N);
    deg_accum_kernel<<<edge_grid, TB>>>(ei, ew, E);
    dis_kernel<<<node_grid, TB>>>(N);
    place_kernel<<<place_grid, TB>>>(ei, ew, E);

    // Layer 1: m = fp16(dis*(x@W1)); h = fp16(relu(b1 + selfloop + messages))
    gemm_msg_kernel<<<gemm_grid, TB>>>(x, 0, W1, p_xwh, N);
    gather_sum_kernel<<<warp8_grid, TB>>>(p_xwh, b1, p_hh, nullptr, 1, N);

    // Layer 2: m = fp16(dis*(h@W2)); out = b2 + selfloop + messages (fp32)
    gemm_msg_kernel<<<gemm_grid, TB>>>(p_hh, 1, W2, p_xwh, N);
    gather_sum_kernel<<<warp8_grid, TB>>>(p_xwh, b2, nullptr, out, 0, N);
}